// round 1
// baseline (speedup 1.0000x reference)
#include <cuda_runtime.h>
#include <math.h>
#include <stdint.h>

#define BATCH 128
#define NANCH 16800
#define NEG_RATIO 3
#define SCALE_XY 10.0f
#define SCALE_WH 5.0f
#define NTHREADS 512

// Per-row scratch (allocation-free rule: __device__ globals)
__device__ float g_row_lossb[BATCH];
__device__ float g_row_lossl[BATCH];
__device__ int   g_row_posn[BATCH];

extern __shared__ unsigned s_bits[];  // NANCH entries: labels_neg as uint bits

__device__ __forceinline__ float warp_sum(float v) {
    #pragma unroll
    for (int o = 16; o > 0; o >>= 1) v += __shfl_down_sync(0xFFFFFFFFu, v, o);
    return v;
}
__device__ __forceinline__ int warp_sum_i(int v) {
    #pragma unroll
    for (int o = 16; o > 0; o >>= 1) v += __shfl_down_sync(0xFFFFFFFFu, v, o);
    return v;
}

__global__ __launch_bounds__(NTHREADS, 1)
void od_row_kernel(const float* __restrict__ pbboxs,
                   const float* __restrict__ plabels,
                   const float* __restrict__ gbboxs,
                   const float* __restrict__ glabels,
                   const float* __restrict__ ancs) {
    const int b   = blockIdx.x;
    const int tid = threadIdx.x;

    __shared__ unsigned hist[256];
    __shared__ float s_sl1, s_bcepos, s_sumgt;
    __shared__ int   s_cnt;
    __shared__ unsigned s_prefix;
    __shared__ int   s_kr;

    if (tid == 0) { s_sl1 = 0.f; s_bcepos = 0.f; s_sumgt = 0.f; s_cnt = 0; }
    __syncthreads();

    const float*  pl = plabels + (size_t)b * NANCH;
    const float*  gl = glabels + (size_t)b * NANCH;
    const float4* pb = (const float4*)pbboxs + (size_t)b * NANCH;
    const float4* gb = (const float4*)gbboxs + (size_t)b * NANCH;
    const float4* an = (const float4*)ancs;

    // ---- Pass 1: BCE everywhere, SmoothL1 only for positives ----
    float acc_sl1 = 0.f, acc_bce = 0.f;
    int cnt = 0;
    for (int i = tid; i < NANCH; i += NTHREADS) {
        float x = pl[i];
        float y = gl[i];
        float bce = fmaxf(x, 0.f) - x * y + log1pf(expf(-fabsf(x)));
        bool pos = (y > 0.f);
        if (pos) {
            float4 p = pb[i];
            float4 g = gb[i];
            float4 a = an[i];
            float inv_az = 1.f / a.z;
            float inv_aw = 1.f / a.w;
            float d0 = p.x - SCALE_XY * (g.x - a.x) * inv_az;
            float d1 = p.y - SCALE_XY * (g.y - a.y) * inv_aw;
            float d2 = p.z - SCALE_WH * logf(g.z * inv_az);
            float d3 = p.w - SCALE_WH * logf(g.w * inv_aw);
            float sl1 = 0.f;
            {
                float ad = fabsf(d0); sl1 += (ad < 1.f) ? 0.5f * d0 * d0 : ad - 0.5f;
                ad = fabsf(d1);       sl1 += (ad < 1.f) ? 0.5f * d1 * d1 : ad - 0.5f;
                ad = fabsf(d2);       sl1 += (ad < 1.f) ? 0.5f * d2 * d2 : ad - 0.5f;
                ad = fabsf(d3);       sl1 += (ad < 1.f) ? 0.5f * d3 * d3 : ad - 0.5f;
            }
            acc_sl1 += sl1;
            acc_bce += bce;
            cnt++;
        }
        s_bits[i] = pos ? 0u : __float_as_uint(bce);  // bce >= 0 so bits order == value order
    }
    // block reduction
    float w1 = warp_sum(acc_sl1);
    float w2 = warp_sum(acc_bce);
    int   w3 = warp_sum_i(cnt);
    if ((tid & 31) == 0) {
        atomicAdd(&s_sl1, w1);
        atomicAdd(&s_bcepos, w2);
        atomicAdd(&s_cnt, w3);
    }
    __syncthreads();

    const int pos_num = s_cnt;
    int K = NEG_RATIO * pos_num;
    if (K > NANCH) K = NANCH;

    float sum_top = 0.f;
    if (K > 0) {
        // ---- Radix select: find K-th largest of s_bits ----
        unsigned prefix = 0;
        int kr = K;
        #pragma unroll
        for (int r = 0; r < 4; r++) {
            const int shift = 24 - 8 * r;
            for (int i = tid; i < 256; i += NTHREADS) hist[i] = 0u;
            __syncthreads();
            for (int i = tid; i < NANCH; i += NTHREADS) {
                unsigned u = s_bits[i];
                if (r == 0 || (u >> (shift + 8)) == prefix)
                    atomicAdd(&hist[(u >> shift) & 255u], 1u);
            }
            __syncthreads();
            if (tid == 0) {
                int cum = 0;
                int bsel = 0;
                for (int bkt = 255; bkt >= 0; bkt--) {
                    cum += (int)hist[bkt];
                    if (cum >= kr) {
                        bsel = bkt;
                        kr -= (cum - (int)hist[bkt]);  // remove strictly-above count
                        break;
                    }
                }
                s_prefix = (prefix << 8) | (unsigned)bsel;
                s_kr = kr;
            }
            __syncthreads();
            prefix = s_prefix;
            kr = s_kr;
            __syncthreads();
        }
        const unsigned T = prefix;     // exact bit pattern of K-th largest value
        const int k_at_T = kr;         // how many copies of T to include

        // ---- Sum of values strictly above T ----
        float sg = 0.f;
        for (int i = tid; i < NANCH; i += NTHREADS) {
            unsigned u = s_bits[i];
            if (u > T) sg += __uint_as_float(u);
        }
        float wg = warp_sum(sg);
        if ((tid & 31) == 0) atomicAdd(&s_sumgt, wg);
        __syncthreads();
        sum_top = s_sumgt + (float)k_at_T * __uint_as_float(T);
    }

    if (tid == 0) {
        g_row_posn[b]  = pos_num;
        g_row_lossb[b] = s_sl1;
        g_row_lossl[b] = s_bcepos + sum_top;
    }
}

__global__ void od_final_kernel(float* out, int out_size) {
    const int t = threadIdx.x;  // BATCH threads
    __shared__ float red[3][4]; // 3 quantities x 4 warps

    float pn   = (float)g_row_posn[t];
    float mask = (pn > 0.f) ? 1.f : 0.f;
    float cntc = fmaxf(pn, 1.1920929e-07f);
    float w    = mask / cntc;

    float vlb = g_row_lossb[t] * w;
    float vll = g_row_lossl[t] * w;
    float vm  = w;

    vlb = warp_sum(vlb);
    vll = warp_sum(vll);
    vm  = warp_sum(vm);
    int wid = t >> 5, lane = t & 31;
    if (lane == 0) { red[0][wid] = vlb; red[1][wid] = vll; red[2][wid] = vm; }
    __syncthreads();
    if (t == 0) {
        float slb = red[0][0] + red[0][1] + red[0][2] + red[0][3];
        float sll = red[1][0] + red[1][1] + red[1][2] + red[1][3];
        float sm  = red[2][0] + red[2][1] + red[2][2] + red[2][3];
        float lb = slb / (float)BATCH;
        float ll = sll / (float)BATCH;
        float total = (lb + ll) * (sm / (float)BATCH);
        if (out_size >= 1) out[0] = total;
        if (out_size >= 2) out[1] = lb;
        if (out_size >= 3) out[2] = ll;
    }
}

extern "C" void kernel_launch(void* const* d_in, const int* in_sizes, int n_in,
                              void* d_out, int out_size) {
    const float* pbboxs  = (const float*)d_in[0];
    const float* plabels = (const float*)d_in[1];
    const float* gbboxs  = (const float*)d_in[2];
    const float* glabels = (const float*)d_in[3];
    const float* ancs    = (const float*)d_in[4];
    (void)in_sizes; (void)n_in;

    const size_t smem = (size_t)NANCH * sizeof(unsigned);
    cudaFuncSetAttribute(od_row_kernel,
                         cudaFuncAttributeMaxDynamicSharedMemorySize, (int)smem);

    od_row_kernel<<<BATCH, NTHREADS, smem>>>(pbboxs, plabels, gbboxs, glabels, ancs);
    od_final_kernel<<<1, BATCH>>>((float*)d_out, out_size);
}

// round 2
// speedup vs baseline: 1.1991x; 1.1991x over previous
#include <cuda_runtime.h>
#include <math.h>
#include <stdint.h>

#define BATCH 128
#define NANCH 16800
#define NQ (NANCH / 4)                       // 4200 float4/uint4 per row
#define NEG_RATIO 3
#define SCALE_XY 10.0f
#define SCALE_WH 5.0f
#define NTHREADS 512
#define NITERS ((NQ + NTHREADS - 1) / NTHREADS)   // 9
#define FLT_EPS_ 1.1920929e-07f

// Per-row scratch + completion counter (allocation-free: __device__ globals)
__device__ float g_row_lossb[BATCH];
__device__ float g_row_lossl[BATCH];
__device__ int   g_row_posn[BATCH];
__device__ int   g_done = 0;

extern __shared__ unsigned s_bits[];  // NANCH entries: labels_neg as uint bits

__device__ __forceinline__ float warp_sum(float v) {
    #pragma unroll
    for (int o = 16; o > 0; o >>= 1) v += __shfl_down_sync(0xFFFFFFFFu, v, o);
    return v;
}
__device__ __forceinline__ int warp_sum_i(int v) {
    #pragma unroll
    for (int o = 16; o > 0; o >>= 1) v += __shfl_down_sync(0xFFFFFFFFu, v, o);
    return v;
}

__global__ __launch_bounds__(NTHREADS, 1)
void od_kernel(const float* __restrict__ pbboxs,
               const float* __restrict__ plabels,
               const float* __restrict__ gbboxs,
               const float* __restrict__ glabels,
               const float* __restrict__ ancs,
               float* __restrict__ out, int out_size) {
    const int b    = blockIdx.x;
    const int tid  = threadIdx.x;
    const int lane = tid & 31;

    __shared__ unsigned hist[256];
    __shared__ float s_sl1, s_bcepos, s_sumgt;
    __shared__ int   s_cnt;
    __shared__ unsigned s_prefix;
    __shared__ int   s_kr;
    __shared__ int   s_last;
    __shared__ float s_red[48];  // 16 warps x 3 quantities

    if (tid == 0) { s_sl1 = 0.f; s_bcepos = 0.f; s_sumgt = 0.f; s_cnt = 0; }
    __syncthreads();

    const float4* pl4 = (const float4*)(plabels + (size_t)b * NANCH);
    const float4* gl4 = (const float4*)(glabels + (size_t)b * NANCH);
    const float4* pb  = (const float4*)pbboxs + (size_t)b * NANCH;
    const float4* gb  = (const float4*)gbboxs + (size_t)b * NANCH;
    const float4* an  = (const float4*)ancs;

    // ---- Pass 1: BCE everywhere (fast softplus), SmoothL1 only for positives ----
    float acc_sl1 = 0.f, acc_bce = 0.f;
    int cnt = 0;
    for (int i4 = tid; i4 < NQ; i4 += NTHREADS) {
        float4 xv = pl4[i4];
        float4 yv = gl4[i4];
        uint4 w;
        #pragma unroll
        for (int c = 0; c < 4; c++) {
            float x = (c == 0) ? xv.x : (c == 1) ? xv.y : (c == 2) ? xv.z : xv.w;
            float y = (c == 0) ? yv.x : (c == 1) ? yv.y : (c == 2) ? yv.z : yv.w;
            float bce = fmaxf(x, 0.f) - x * y + __logf(1.f + __expf(-fabsf(x)));
            unsigned bits;
            if (y > 0.f) {
                const int i = 4 * i4 + c;
                float4 p = pb[i];
                float4 g = gb[i];
                float4 a = an[i];
                float inv_az = 1.f / a.z;
                float inv_aw = 1.f / a.w;
                float d0 = p.x - SCALE_XY * (g.x - a.x) * inv_az;
                float d1 = p.y - SCALE_XY * (g.y - a.y) * inv_aw;
                float d2 = p.z - SCALE_WH * __logf(g.z * inv_az);
                float d3 = p.w - SCALE_WH * __logf(g.w * inv_aw);
                float sl1 = 0.f, ad;
                ad = fabsf(d0); sl1 += (ad < 1.f) ? 0.5f * d0 * d0 : ad - 0.5f;
                ad = fabsf(d1); sl1 += (ad < 1.f) ? 0.5f * d1 * d1 : ad - 0.5f;
                ad = fabsf(d2); sl1 += (ad < 1.f) ? 0.5f * d2 * d2 : ad - 0.5f;
                ad = fabsf(d3); sl1 += (ad < 1.f) ? 0.5f * d3 * d3 : ad - 0.5f;
                acc_sl1 += sl1;
                acc_bce += bce;
                cnt++;
                bits = 0u;
            } else {
                bits = __float_as_uint(bce);  // bce >= 0: bit order == value order
            }
            if (c == 0) w.x = bits; else if (c == 1) w.y = bits;
            else if (c == 2) w.z = bits; else w.w = bits;
        }
        ((uint4*)s_bits)[i4] = w;
    }
    {
        float w1 = warp_sum(acc_sl1);
        float w2 = warp_sum(acc_bce);
        int   w3 = warp_sum_i(cnt);
        if (lane == 0) {
            atomicAdd(&s_sl1, w1);
            atomicAdd(&s_bcepos, w2);
            atomicAdd(&s_cnt, w3);
        }
    }
    __syncthreads();

    const int pos_num = s_cnt;
    int K = NEG_RATIO * pos_num;
    if (K > NANCH) K = NANCH;

    float sum_top = 0.f;
    if (K > 0) {
        // ---- 3-round radix select (24-bit threshold), match-aggregated histogram ----
        unsigned prefix = 0;
        int kr = K;
        #pragma unroll
        for (int r = 0; r < 3; r++) {
            const int shift = 24 - 8 * r;
            if (tid < 256) hist[tid] = 0u;
            __syncthreads();

            for (int it = 0; it < NITERS; it++) {
                const int i4 = tid + it * NTHREADS;
                uint4 w = make_uint4(0, 0, 0, 0);
                const bool valid = (i4 < NQ);
                if (valid) w = ((const uint4*)s_bits)[i4];
                #pragma unroll
                for (int c = 0; c < 4; c++) {
                    unsigned u = (c == 0) ? w.x : (c == 1) ? w.y : (c == 2) ? w.z : w.w;
                    bool ok = valid && (r == 0 || (u >> (shift + 8)) == prefix);
                    unsigned bkt = ok ? ((u >> shift) & 255u) : 0xFFFFFFFFu;
                    unsigned m = __match_any_sync(0xFFFFFFFFu, bkt);
                    if (ok && lane == (__ffs(m) - 1))
                        atomicAdd(&hist[bkt], (unsigned)__popc(m));
                }
            }
            __syncthreads();

            // Warp 0: parallel descending suffix-scan over 256 bins
            if (tid < 32) {
                int s[8];
                int run = 0;
                #pragma unroll
                for (int j = 0; j < 8; j++) {
                    run += (int)hist[255 - (tid * 8 + j)];
                    s[j] = run;
                }
                const int tot = run;
                int incl = tot;
                #pragma unroll
                for (int o = 1; o < 32; o <<= 1) {
                    int v = __shfl_up_sync(0xFFFFFFFFu, incl, o);
                    if (lane >= o) incl += v;
                }
                const int excl = incl - tot;
                int found_j = -1;
                #pragma unroll
                for (int j = 0; j < 8; j++)
                    if (found_j < 0 && excl + s[j] >= kr) found_j = j;
                unsigned bal = __ballot_sync(0xFFFFFFFFu, found_j >= 0);
                int winner = __ffs(bal) - 1;
                if (lane == winner) {
                    const int idx = 255 - (tid * 8 + found_j);
                    s_prefix = (prefix << 8) | (unsigned)idx;
                    s_kr = kr - (excl + s[found_j] - (int)hist[idx]);
                }
            }
            __syncthreads();
            prefix = s_prefix;
            kr = s_kr;
        }

        // ---- Sum strictly above the selected 24-bit bin; approximate bin by midpoint ----
        float sg = 0.f;
        for (int i4 = tid; i4 < NQ; i4 += NTHREADS) {
            uint4 w = ((const uint4*)s_bits)[i4];
            if ((w.x >> 8) > prefix) sg += __uint_as_float(w.x);
            if ((w.y >> 8) > prefix) sg += __uint_as_float(w.y);
            if ((w.z >> 8) > prefix) sg += __uint_as_float(w.z);
            if ((w.w >> 8) > prefix) sg += __uint_as_float(w.w);
        }
        float wg = warp_sum(sg);
        if (lane == 0) atomicAdd(&s_sumgt, wg);
        __syncthreads();
        sum_top = s_sumgt + (float)kr * __uint_as_float((prefix << 8) | 0x80u);
    }

    // ---- Publish row result; last block reduces and writes output ----
    if (tid == 0) {
        g_row_posn[b]  = pos_num;
        g_row_lossb[b] = s_sl1;
        g_row_lossl[b] = s_bcepos + sum_top;
        __threadfence();
        int prev = atomicAdd(&g_done, 1);
        s_last = (prev == BATCH - 1);
    }
    __syncthreads();

    if (s_last) {
        float vlb = 0.f, vll = 0.f, vm = 0.f;
        if (tid < BATCH) {
            float pn  = (float)((volatile int*)g_row_posn)[tid];
            float lbv = ((volatile float*)g_row_lossb)[tid];
            float llv = ((volatile float*)g_row_lossl)[tid];
            float mask = (pn > 0.f) ? 1.f : 0.f;
            float wgt  = mask / fmaxf(pn, FLT_EPS_);
            vlb = lbv * wgt;
            vll = llv * wgt;
            vm  = wgt;
        }
        vlb = warp_sum(vlb);
        vll = warp_sum(vll);
        vm  = warp_sum(vm);
        const int wid = tid >> 5;
        if (lane == 0) {
            s_red[wid * 3 + 0] = vlb;
            s_red[wid * 3 + 1] = vll;
            s_red[wid * 3 + 2] = vm;
        }
        __syncthreads();
        if (tid == 0) {
            float slb = 0.f, sll = 0.f, sm = 0.f;
            #pragma unroll
            for (int w = 0; w < 16; w++) {
                slb += s_red[w * 3 + 0];
                sll += s_red[w * 3 + 1];
                sm  += s_red[w * 3 + 2];
            }
            const float lb = slb / (float)BATCH;
            const float ll = sll / (float)BATCH;
            const float total = (lb + ll) * (sm / (float)BATCH);
            if (out_size >= 1) out[0] = total;
            if (out_size >= 2) out[1] = lb;
            if (out_size >= 3) out[2] = ll;
            g_done = 0;  // reset for next graph replay
        }
    }
}

extern "C" void kernel_launch(void* const* d_in, const int* in_sizes, int n_in,
                              void* d_out, int out_size) {
    const float* pbboxs  = (const float*)d_in[0];
    const float* plabels = (const float*)d_in[1];
    const float* gbboxs  = (const float*)d_in[2];
    const float* glabels = (const float*)d_in[3];
    const float* ancs    = (const float*)d_in[4];
    (void)in_sizes; (void)n_in;

    const size_t smem = (size_t)NANCH * sizeof(unsigned);
    cudaFuncSetAttribute(od_kernel,
                         cudaFuncAttributeMaxDynamicSharedMemorySize, (int)smem);

    od_kernel<<<BATCH, NTHREADS, smem>>>(pbboxs, plabels, gbboxs, glabels, ancs,
                                         (float*)d_out, out_size);
}